// round 12
// baseline (speedup 1.0000x reference)
#include <cuda_runtime.h>
#include <cuda_bf16.h>
#include <math.h>

// AvULoss fused single-kernel. R11: per-WARP cp.async double-buffered pipelines
// (cp.async groups are per-thread state) -> no __syncthreads in the main loop,
// warps drift out of phase, DRAM issuance is continuous instead of convoyed.
// Packed f32x2 softmax math, entropy identity, deterministic last-block reduce.

#define C 32
#define WARPS 4
#define BLOCK (WARPS * 32)
#define WTILE 32              // rows per warp-tile
#define ROW_PAD 36            // 144B/row -> conflict-free 16B shared loads
#define GRID_MAX 1184
#define EPS 1e-10
#define L2E 1.4426950408889634f
#define LN2 0.6931471805599453f

__device__ float4 g_partials[GRID_MAX];
__device__ unsigned int g_count = 0;

typedef unsigned long long u64;

__device__ __forceinline__ void cp16(float* smem_dst, const float4* gsrc) {
    unsigned s = (unsigned)__cvta_generic_to_shared(smem_dst);
    asm volatile("cp.async.cg.shared.global [%0], [%1], 16;\n" :: "r"(s), "l"(gsrc));
}
__device__ __forceinline__ void cp_commit() { asm volatile("cp.async.commit_group;\n"); }
__device__ __forceinline__ void cp_wait1()  { asm volatile("cp.async.wait_group 1;\n" ::: "memory"); }

__device__ __forceinline__ u64 pack2(float lo, float hi) {
    u64 r; asm("mov.b64 %0, {%1, %2};" : "=l"(r) : "f"(lo), "f"(hi)); return r;
}
__device__ __forceinline__ void unpack2(u64 p, float& lo, float& hi) {
    asm("mov.b64 {%0, %1}, %2;" : "=f"(lo), "=f"(hi) : "l"(p));
}
__device__ __forceinline__ u64 add2(u64 a, u64 b) {
    u64 r; asm("add.rn.f32x2 %0, %1, %2;" : "=l"(r) : "l"(a), "l"(b)); return r;
}
__device__ __forceinline__ u64 fma2(u64 a, u64 b, u64 c) {
    u64 r; asm("fma.rn.f32x2 %0, %1, %2, %3;" : "=l"(r) : "l"(a), "l"(b), "l"(c)); return r;
}
__device__ __forceinline__ float ex2f(float x) {
    float r; asm("ex2.approx.f32 %0, %1;" : "=f"(r) : "f"(x)); return r;
}
__device__ __forceinline__ void lds_v2b64(unsigned addr, u64& a, u64& b) {
    asm volatile("ld.shared.v2.b64 {%0, %1}, [%2];" : "=l"(a), "=l"(b) : "r"(addr));
}

__global__ __launch_bounds__(BLOCK, 6) void avu_fused_kernel(
    const float* __restrict__ logits,
    const int* __restrict__ labels,
    float* __restrict__ out,
    int n_rows, int nwtiles)
{
    // per-warp private double buffers: [warp][buf][32 rows * ROW_PAD]
    __shared__ float sm[WARPS][2][WTILE * ROW_PAD];

    const int tid  = threadIdx.x;
    const int lane = tid & 31, warp = tid >> 5;
    const float4* g = (const float4*)logits;
    const long long total_f4 = (long long)n_rows * (C / 4);
    const u64 l2e2 = pack2(L2E, L2E);

    const int gw      = blockIdx.x * WARPS + warp;   // global warp id
    const int gstride = gridDim.x * WARPS;

    float ac = 0.f, au = 0.f, ic = 0.f, iu = 0.f;

    // ---- Prologue: stage first warp-tile into buffer 0 ----
    if (gw < nwtiles) {
        const long long base_f4 = (long long)gw * WTILE * (C / 4);
        #pragma unroll
        for (int k = 0; k < 8; k++) {
            int idx = lane + k * 32;                 // 0..255
            float* dst = &sm[warp][0][(idx >> 3) * ROW_PAD + (idx & 7) * 4];
            if (base_f4 + idx < total_f4) cp16(dst, &g[base_f4 + idx]);
            else *(float4*)dst = make_float4(0.f, 0.f, 0.f, 0.f);
        }
    }
    cp_commit();

    int pb = 0;
    for (int tile = gw; tile < nwtiles; tile += gstride) {
        // ---- Prefetch next warp-tile into the other buffer ----
        int tn = tile + gstride;
        if (tn < nwtiles) {
            const long long base_f4 = (long long)tn * WTILE * (C / 4);
            if ((long long)(tn + 1) * WTILE <= n_rows) {
                #pragma unroll
                for (int k = 0; k < 8; k++) {
                    int idx = lane + k * 32;
                    cp16(&sm[warp][pb ^ 1][(idx >> 3) * ROW_PAD + (idx & 7) * 4],
                         &g[base_f4 + idx]);
                }
            } else {
                #pragma unroll
                for (int k = 0; k < 8; k++) {
                    int idx = lane + k * 32;
                    float* dst = &sm[warp][pb ^ 1][(idx >> 3) * ROW_PAD + (idx & 7) * 4];
                    if (base_f4 + idx < total_f4) cp16(dst, &g[base_f4 + idx]);
                    else *(float4*)dst = make_float4(0.f, 0.f, 0.f, 0.f);
                }
            }
        }
        cp_commit();                 // per-thread group count stays in lockstep
        cp_wait1();                  // this thread's copies for current tile done
        __syncwarp();                // all lanes' copies done -> buffer complete

        // ---- Compute from buffer pb: one row per lane ----
        const long long my_row = (long long)tile * WTILE + lane;
        if (my_row < n_rows) {
            const float* r = &sm[warp][pb][lane * ROW_PAD];
            unsigned raddr = (unsigned)__cvta_generic_to_shared(r);

            u64 lp[16];
            #pragma unroll
            for (int j = 0; j < 8; j++)
                lds_v2b64(raddr + j * 16, lp[2 * j], lp[2 * j + 1]);

            float l[C];
            #pragma unroll
            for (int i = 0; i < 16; i++) unpack2(lp[i], l[2 * i], l[2 * i + 1]);

            float m0 = l[0];
            #pragma unroll
            for (int j = 1; j < C; j++) m0 = fmaxf(m0, l[j]);

            // packed: t = l*L2E - m0*L2E ; e = 2^t ; S += e ; dt += e*t
            const u64 nm2 = pack2(-m0 * L2E, -m0 * L2E);
            u64 S2a = 0, S2b = 0, D2a = 0, D2b = 0;
            #pragma unroll
            for (int i = 0; i < 16; i += 2) {
                u64 t2a = fma2(lp[i],     l2e2, nm2);
                u64 t2b = fma2(lp[i + 1], l2e2, nm2);
                float ta0, ta1, tb0, tb1;
                unpack2(t2a, ta0, ta1);
                unpack2(t2b, tb0, tb1);
                u64 e2a = pack2(ex2f(ta0), ex2f(ta1));
                u64 e2b = pack2(ex2f(tb0), ex2f(tb1));
                S2a = add2(S2a, e2a);
                S2b = add2(S2b, e2b);
                D2a = fma2(e2a, t2a, D2a);
                D2b = fma2(e2b, t2b, D2b);
            }
            float s0, s1, s2, s3, d0, d1, d2, d3;
            unpack2(S2a, s0, s1); unpack2(S2b, s2, s3);
            unpack2(D2a, d0, d1); unpack2(D2b, d2, d3);
            float S   = (s0 + s1) + (s2 + s3);
            float dot = ((d0 + d1) + (d2 + d3)) * LN2;   // back to nats

            float invS = __fdividef(1.0f, S);
            float conf = invS;                           // max prob = exp(0)/S
            float unc  = __logf(S) - dot * invS;         // entropy identity
            float t;
            asm("tanh.approx.f32 %0, %1;" : "=f"(t) : "f"(unc));

            int lab = __ldg(&labels[my_row]);
            bool accurate = (r[lab] == m0);              // ties measure-zero
            bool certain  = (unc <= 1.0f);

            float wA = accurate ? conf : (1.0f - conf);
            float w  = wA * (certain ? (1.0f - t) : t);

            if (accurate) { if (certain) ac += w; else au += w; }
            else          { if (certain) ic += w; else iu += w; }
        }
        __syncwarp();                // lanes done reading before re-stage
        pb ^= 1;
    }

    // ---- Block reduction (deterministic shuffle tree) ----
    #pragma unroll
    for (int off = 16; off > 0; off >>= 1) {
        ac += __shfl_down_sync(0xffffffffu, ac, off);
        au += __shfl_down_sync(0xffffffffu, au, off);
        ic += __shfl_down_sync(0xffffffffu, ic, off);
        iu += __shfl_down_sync(0xffffffffu, iu, off);
    }
    __shared__ float4 warp_part[WARPS];
    __shared__ bool   s_last;
    if (lane == 0) warp_part[warp] = make_float4(ac, au, ic, iu);
    __syncthreads();

    if (tid == 0) {
        float4 s = warp_part[0];
        #pragma unroll
        for (int w = 1; w < WARPS; w++) {
            float4 p = warp_part[w];
            s.x += p.x; s.y += p.y; s.z += p.z; s.w += p.w;
        }
        g_partials[blockIdx.x] = s;
        __threadfence();
        unsigned prev = atomicAdd(&g_count, 1u);
        s_last = (prev == gridDim.x - 1);
    }
    __syncthreads();

    // ---- Last block: deterministic fixed-order final reduce ----
    if (s_last) {
        double a = 0.0, b = 0.0, c = 0.0, d = 0.0;
        for (int i = tid; i < (int)gridDim.x; i += BLOCK) {
            float4 p = g_partials[i];
            a += p.x; b += p.y; c += p.z; d += p.w;
        }
        #pragma unroll
        for (int off = 16; off > 0; off >>= 1) {
            a += __shfl_down_sync(0xffffffffu, a, off);
            b += __shfl_down_sync(0xffffffffu, b, off);
            c += __shfl_down_sync(0xffffffffu, c, off);
            d += __shfl_down_sync(0xffffffffu, d, off);
        }
        __shared__ double sd[WARPS][4];
        if (lane == 0) { sd[warp][0] = a; sd[warp][1] = b; sd[warp][2] = c; sd[warp][3] = d; }
        __syncthreads();
        if (tid == 0) {
            double A = 0, B = 0, Cc = 0, D = 0;
            #pragma unroll
            for (int w = 0; w < WARPS; w++) {
                A += sd[w][0]; B += sd[w][1]; Cc += sd[w][2]; D += sd[w][3];
            }
            double avu = (A + D) / (A + B + Cc + D + EPS);
            out[0] = (float)(-log(avu + EPS));
            g_count = 0;             // reset for next graph replay
        }
    }
}

extern "C" void kernel_launch(void* const* d_in, const int* in_sizes, int n_in,
                              void* d_out, int out_size)
{
    const float* logits = (const float*)d_in[0];
    const int*   labels = (const int*)d_in[1];     // int32 (JAX default)
    float* out = (float*)d_out;

    int n_rows  = in_sizes[1];
    int nwtiles = (n_rows + WTILE - 1) / WTILE;    // 65536 for N=2^21

    int grid = 148 * 6;
    if (grid > GRID_MAX) grid = GRID_MAX;
    int maxg = (nwtiles + WARPS - 1) / WARPS;
    if (grid > maxg) grid = maxg;

    avu_fused_kernel<<<grid, BLOCK>>>(logits, labels, out, n_rows, nwtiles);
}